// round 1
// baseline (speedup 1.0000x reference)
#include <cuda_runtime.h>

#define NCODES 4096
#define DIM 64
#define NPTS 65536      // B*S = 16*4096
#define TILE 128
#define DECAY_F 0.99f
#define OMD_F 0.01f     // 1 - DECAY
#define EPS_F 1e-5f

// Scratch (no allocations allowed — __device__ globals)
__device__ float g_counts[NCODES];
__device__ float g_embed[NCODES * DIM];
__device__ float g_csq[NCODES];
__device__ float g_factor[NCODES];
__device__ float g_ncs[NCODES];

// ---- packed f32x2 helpers (sm_100+: fma.rn.f32x2 — 2x fp32 FMA per issue) ----
__device__ __forceinline__ unsigned long long fma2(unsigned long long a,
                                                   unsigned long long b,
                                                   unsigned long long c) {
    unsigned long long d;
    asm("fma.rn.f32x2 %0, %1, %2, %3;" : "=l"(d) : "l"(a), "l"(b), "l"(c));
    return d;
}
__device__ __forceinline__ unsigned long long add2(unsigned long long a,
                                                   unsigned long long b) {
    unsigned long long d;
    asm("add.rn.f32x2 %0, %1, %2;" : "=l"(d) : "l"(a), "l"(b));
    return d;
}
__device__ __forceinline__ float2 unpack2(unsigned long long v) {
    unsigned int lo, hi;
    asm("mov.b64 {%0, %1}, %2;" : "=r"(lo), "=r"(hi) : "l"(v));
    return make_float2(__uint_as_float(lo), __uint_as_float(hi));
}

// ---- Kernel 0: zero scratch + compute ||c_k||^2 ----
__global__ void prep_kernel(const float* __restrict__ codebook) {
    int i = blockIdx.x * blockDim.x + threadIdx.x;
    if (i < NCODES * DIM) g_embed[i] = 0.0f;
    if (i < NCODES) {
        g_counts[i] = 0.0f;
        const float4* row = (const float4*)(codebook + (size_t)i * DIM);
        float s = 0.0f;
#pragma unroll
        for (int j = 0; j < 16; j++) {
            float4 v = row[j];
            s += v.x * v.x;
            s += v.y * v.y;
            s += v.z * v.z;
            s += v.w * v.w;
        }
        g_csq[i] = s;
    }
}

// ---- Kernel 1: fused argmin + quantize-gather + EMA scatter ----
// One thread per point. Codebook streamed through shared in 128-code tiles.
// score = ||c||^2 - 2 x.c (x_sq dropped: constant per point, argmin-invariant).
__global__ void __launch_bounds__(256, 2) argmin_kernel(
    const float* __restrict__ x, const float* __restrict__ codebook,
    float* __restrict__ o_quant, float* __restrict__ o_idx) {
    __shared__ float4 sc[TILE * 16];  // 128 codes x 64 floats = 32 KB
    __shared__ float scsq[TILE];

    const int pt = blockIdx.x * 256 + threadIdx.x;

    // Point vector in registers as 32 packed f32x2 (64 floats).
    unsigned long long xv[32];
    {
        const ulonglong2* xr = (const ulonglong2*)(x + (size_t)pt * DIM);
#pragma unroll
        for (int j = 0; j < 16; j++) {
            ulonglong2 v = xr[j];
            xv[2 * j + 0] = v.x;
            xv[2 * j + 1] = v.y;
        }
    }

    float bestd = 3.4e38f;
    int besti = 0;

    const float4* cb4 = (const float4*)codebook;

    for (int t = 0; t < NCODES / TILE; ++t) {
        // Cooperative tile load: 2048 float4s by 256 threads (coalesced).
#pragma unroll
        for (int j = 0; j < 8; j++)
            sc[threadIdx.x + j * 256] = cb4[t * (TILE * 16) + threadIdx.x + j * 256];
        if (threadIdx.x < TILE) scsq[threadIdx.x] = g_csq[t * TILE + threadIdx.x];
        __syncthreads();

#pragma unroll 2
        for (int kk = 0; kk < TILE; ++kk) {
            const ulonglong2* crow = (const ulonglong2*)(sc + kk * 16);
            unsigned long long a0 = 0ull, a1 = 0ull, a2 = 0ull, a3 = 0ull;
#pragma unroll
            for (int j = 0; j < 8; j++) {
                ulonglong2 c0 = crow[2 * j + 0];  // LDS128, warp-broadcast
                ulonglong2 c1 = crow[2 * j + 1];
                a0 = fma2(xv[4 * j + 0], c0.x, a0);
                a1 = fma2(xv[4 * j + 1], c0.y, a1);
                a2 = fma2(xv[4 * j + 2], c1.x, a2);
                a3 = fma2(xv[4 * j + 3], c1.y, a3);
            }
            unsigned long long s = add2(add2(a0, a1), add2(a2, a3));
            float2 f = unpack2(s);
            float d = scsq[kk] - 2.0f * (f.x + f.y);
            // strict < with ascending k == argmin first-occurrence tie-break
            if (d < bestd) {
                bestd = d;
                besti = t * TILE + kk;
            }
        }
        __syncthreads();
    }

    // indices output (as float, per concatenated f32 output convention)
    o_idx[pt] = (float)besti;

    // quantized = codebook[besti] (codebook is 1 MB, L2-resident)
    {
        float4* q = (float4*)(o_quant + (size_t)pt * DIM);
        const float4* cr = (const float4*)(codebook + (size_t)besti * DIM);
#pragma unroll
        for (int j = 0; j < 16; j++) q[j] = cr[j];
    }

    // EMA scatter-accumulate
    atomicAdd(&g_counts[besti], 1.0f);
    float* es = g_embed + (size_t)besti * DIM;
#pragma unroll
    for (int j = 0; j < 32; j++) {
        float2 f = unpack2(xv[j]);
        atomicAdd(&es[2 * j + 0], f.x);
        atomicAdd(&es[2 * j + 1], f.y);
    }
}

// ---- Kernel 2: new_cluster_size, n-reduction, smoothing reciprocal ----
__global__ void finalize1_kernel(const float* __restrict__ cluster_size,
                                 float* __restrict__ o_cs) {
    __shared__ float warpsum[32];
    __shared__ float s_n;
    float local = 0.0f;
    for (int k = threadIdx.x; k < NCODES; k += blockDim.x) {
        float ncs = DECAY_F * cluster_size[k] + OMD_F * g_counts[k];
        o_cs[k] = ncs;
        g_ncs[k] = ncs;
        local += ncs;
    }
#pragma unroll
    for (int o = 16; o; o >>= 1) local += __shfl_down_sync(0xffffffffu, local, o);
    if ((threadIdx.x & 31) == 0) warpsum[threadIdx.x >> 5] = local;
    __syncthreads();
    if (threadIdx.x < 32) {
        float v = (threadIdx.x < (blockDim.x >> 5)) ? warpsum[threadIdx.x] : 0.0f;
#pragma unroll
        for (int o = 16; o; o >>= 1) v += __shfl_down_sync(0xffffffffu, v, o);
        if (threadIdx.x == 0) s_n = v;
    }
    __syncthreads();
    float n = s_n;
    float denom = n + (float)NCODES * EPS_F;
    for (int k = threadIdx.x; k < NCODES; k += blockDim.x) {
        float sm = (g_ncs[k] + EPS_F) / denom * n;
        g_factor[k] = 1.0f / sm;
    }
}

// ---- Kernel 3: new_ema_w and new_codebook ----
__global__ void finalize2_kernel(const float* __restrict__ ema_w,
                                 float* __restrict__ o_cb,
                                 float* __restrict__ o_ema) {
    int i = blockIdx.x * blockDim.x + threadIdx.x;
    if (i >= NCODES * DIM) return;
    float e = DECAY_F * ema_w[i] + OMD_F * g_embed[i];
    o_ema[i] = e;
    o_cb[i] = e * g_factor[i >> 6];
}

extern "C" void kernel_launch(void* const* d_in, const int* in_sizes, int n_in,
                              void* d_out, int out_size) {
    const float* x            = (const float*)d_in[0];
    const float* codebook     = (const float*)d_in[1];
    const float* cluster_size = (const float*)d_in[2];
    const float* ema_w        = (const float*)d_in[3];

    float* out     = (float*)d_out;
    float* o_quant = out;                               // 16*4096*64
    float* o_idx   = o_quant + (size_t)NPTS * DIM;      // 16*4096
    float* o_cb    = o_idx + NPTS;                      // 4096*64
    float* o_cs    = o_cb + (size_t)NCODES * DIM;       // 4096
    float* o_ema   = o_cs + NCODES;                     // 4096*64

    prep_kernel<<<(NCODES * DIM + 255) / 256, 256>>>(codebook);
    argmin_kernel<<<NPTS / 256, 256>>>(x, codebook, o_quant, o_idx);
    finalize1_kernel<<<1, 1024>>>(cluster_size, o_cs);
    finalize2_kernel<<<(NCODES * DIM + 255) / 256, 256>>>(ema_w, o_cb, o_ema);
}

// round 3
// speedup vs baseline: 1.8829x; 1.8829x over previous
#include <cuda_runtime.h>

#define NCODES 4096
#define DIM 64
#define NPTS 65536          // B*S
#define NTIL 32             // code tiles of 128
#define TILE_FLOATS 16512   // 16384 packed B floats + 128 csq
#define DECAY_F 0.99f
#define OMD_F 0.01f
#define EPS_F 1e-5f

// ---------------- device scratch (no allocations allowed) ----------------
__device__ float g_counts[NCODES];
__device__ float g_embed[NCODES * DIM];
__device__ float g_ncs[NCODES];
__device__ float g_factor[NCODES];
// Codebook split to tf32 hi/lo, pre-packed in mma.sync m16n8k8 B-fragment
// order (one LDS.128 per lane per 2 k-steps), csq appended per tile block.
__device__ __align__(128) float g_cbB[NTIL * TILE_FLOATS];

// ---------------- smem layout (bytes) ----------------
#define OFF_A    0            // packed A frags: 2 splits x 8 kstep x 8 mtile x 32 lanes x 16B = 64KB
#define OFF_B    65536        // 2 bufs x 64KB packed B
#define OFF_CSQ  196608       // 2 x 128 floats
#define OFF_XSQ  197632       // 128 floats
#define OFF_MD   198144       // 2 x 128 floats (merge dist)
#define OFF_MI   199168       // 2 x 128 ints  (merge idx)
#define SMEM_TOTAL 200192

static __device__ __forceinline__ float tf32r(float v) {
    unsigned u;
    asm("cvt.rna.tf32.f32 %0, %1;" : "=r"(u) : "f"(v));
    return __uint_as_float(u);
}

static __device__ __forceinline__ void mma8(float* c, const uint4& a,
                                            unsigned b0, unsigned b1) {
    asm("mma.sync.aligned.m16n8k8.row.col.f32.tf32.tf32.f32 "
        "{%0,%1,%2,%3}, {%4,%5,%6,%7}, {%8,%9}, {%0,%1,%2,%3};"
        : "+f"(c[0]), "+f"(c[1]), "+f"(c[2]), "+f"(c[3])
        : "r"(a.x), "r"(a.y), "r"(a.z), "r"(a.w), "r"(b0), "r"(b1));
}

static __device__ __forceinline__ void cp16(unsigned dst, const void* src) {
    asm volatile("cp.async.cg.shared.global [%0], [%1], 16;" :: "r"(dst), "l"(src));
}
#define CP_COMMIT() asm volatile("cp.async.commit_group;" ::: "memory")
#define CP_WAIT1()  asm volatile("cp.async.wait_group 1;" ::: "memory")

// ---- prep: split codebook to tf32 hi/lo in packed fragment layout + csq ----
// Element (code k, dim d) -> tile=k>>7, n=k&127:
//  float idx in tile block = (((split*4 + (d>>4))*16 + (n>>3))*32
//                             + ((n&7)*4 + (d&3)))*4 + ((d>>3)&1)*2 + ((d&7)>>2)
__global__ void prep_kernel(const float* __restrict__ codebook) {
    int i = blockIdx.x * blockDim.x + threadIdx.x;  // 0..262143
    if (i >= NCODES * DIM) return;
    int k = i >> 6, d = i & 63;
    float v = codebook[i];
    float hf = tf32r(v);
    float lf = tf32r(v - hf);
    int tile = k >> 7, n = k & 127;
    int reg = ((d >> 3) & 1) * 2 + ((d & 7) >> 2);
    int lane = (n & 7) * 4 + (d & 3);
    float* base = g_cbB + (size_t)tile * TILE_FLOATS;
    base[(((0 * 4 + (d >> 4)) * 16 + (n >> 3)) * 32 + lane) * 4 + reg] = hf;
    base[(((1 * 4 + (d >> 4)) * 16 + (n >> 3)) * 32 + lane) * 4 + reg] = lf;
    g_embed[i] = 0.0f;
    if (d == 0) {
        g_counts[k] = 0.0f;
        const float* row = codebook + (size_t)k * DIM;
        float s = 0.0f;
#pragma unroll
        for (int j = 0; j < DIM; j++) s += row[j] * row[j];
        base[16384 + n] = s;  // csq appended per tile
    }
}

// ---- main: tf32 3-pass mma.sync GEMM + fused argmin + EMA scatter ----
__global__ void __launch_bounds__(256, 1) vq_kernel(
    const float* __restrict__ x, const float* __restrict__ codebook,
    float* __restrict__ o_quant, float* __restrict__ o_idx) {
    extern __shared__ char smem[];
    const int tid = threadIdx.x;
    const int lane = tid & 31, w = tid >> 5;
    const int rw = w >> 1, cw = w & 1;  // row-warp 0..3 (32 pts), col-warp 0..1 (64 codes)

    float* A_s = (float*)(smem + OFF_A);
    float* xsq_s = (float*)(smem + OFF_XSQ);

    // --- prologue: pack x tile into A-fragment layout, compute xsq ---
    if (tid < 128) {
        const int m = tid;
        const float4* xr = (const float4*)(x + ((size_t)blockIdx.x * 128 + m) * DIM);
        float s = 0.0f;
        const int mt = m >> 4;
        const int rh = (m >> 3) & 1;
        const int lbase = (m & 7) * 4;
#pragma unroll
        for (int j = 0; j < 16; j++) {
            float4 v4 = xr[j];
            float vv[4] = {v4.x, v4.y, v4.z, v4.w};
#pragma unroll
            for (int e = 0; e < 4; e++) {
                int d = j * 4 + e;
                float v = vv[e];
                float hf = tf32r(v);
                float lf = tf32r(v - hf);
                int kstep = d >> 3;
                int reg = ((d & 7) >> 2) * 2 + rh;
                int ln = lbase + (d & 3);
                A_s[(((0 * 8 + kstep) * 8 + mt) * 32 + ln) * 4 + reg] = hf;
                A_s[(((1 * 8 + kstep) * 8 + mt) * 32 + ln) * 4 + reg] = lf;
                s += v * v;
            }
        }
        xsq_s[m] = s;
    }

    // --- prefetch tiles 0,1 via cp.async ---
    const unsigned smem_b0 = (unsigned)__cvta_generic_to_shared(smem + OFF_B);
    const unsigned smem_csq = (unsigned)__cvta_generic_to_shared(smem + OFF_CSQ);
#pragma unroll
    for (int t = 0; t < 2; t++) {
        const float* src = g_cbB + (size_t)t * TILE_FLOATS;
        for (int c = tid; c < 4128; c += 256) {
            unsigned dst = (c < 4096) ? (smem_b0 + t * 65536 + c * 16)
                                      : (smem_csq + t * 512 + (c - 4096) * 16);
            cp16(dst, src + c * 4);
        }
        CP_COMMIT();
    }
    __syncthreads();  // A pack + xsq visible

    // per-lane argmin state: slot = mt*2 + rh
    float bestd[4] = {3.4e38f, 3.4e38f, 3.4e38f, 3.4e38f};
    int besti[4] = {0, 0, 0, 0};
    float xsq_r[4];
#pragma unroll
    for (int mt = 0; mt < 2; mt++)
#pragma unroll
        for (int rh = 0; rh < 2; rh++)
            xsq_r[mt * 2 + rh] = xsq_s[32 * rw + mt * 16 + rh * 8 + (lane >> 2)];

    const uint4* A4 = (const uint4*)(smem + OFF_A);

    for (int t = 0; t < NTIL; ++t) {
        const int buf = t & 1;
        CP_WAIT1();
        __syncthreads();

        float acc[64];
#pragma unroll
        for (int i = 0; i < 64; i++) acc[i] = 0.0f;

        const uint4* B4 = (const uint4*)(smem + OFF_B + buf * 65536);

#pragma unroll 1
        for (int pass = 0; pass < 3; pass++) {
            // pass0: Ahi*Bhi  pass1: Alo*Bhi  pass2: Ahi*Blo
            const uint4* Ap = A4 + ((pass == 1) ? 2048 : 0);
            const uint4* Bp = B4 + ((pass == 2) ? 2048 : 0);
#pragma unroll
            for (int ksp = 0; ksp < 4; ksp++) {
                uint4 ae0 = Ap[(((ksp * 2 + 0) * 8) + 2 * rw + 0) * 32 + lane];
                uint4 ao0 = Ap[(((ksp * 2 + 1) * 8) + 2 * rw + 0) * 32 + lane];
                uint4 ae1 = Ap[(((ksp * 2 + 0) * 8) + 2 * rw + 1) * 32 + lane];
                uint4 ao1 = Ap[(((ksp * 2 + 1) * 8) + 2 * rw + 1) * 32 + lane];
#pragma unroll
                for (int nt = 0; nt < 8; nt++) {
                    uint4 b = Bp[(ksp * 16 + cw * 8 + nt) * 32 + lane];
                    mma8(&acc[(0 * 8 + nt) * 4], ae0, b.x, b.y);
                    mma8(&acc[(0 * 8 + nt) * 4], ao0, b.z, b.w);
                    mma8(&acc[(1 * 8 + nt) * 4], ae1, b.x, b.y);
                    mma8(&acc[(1 * 8 + nt) * 4], ao1, b.z, b.w);
                }
            }
        }

        // --- argmin epilogue (exact fp32 combine, matches reference order) ---
        const float* csq = (const float*)(smem + OFF_CSQ + buf * 512);
        const int kb = t * 128 + cw * 64;
#pragma unroll
        for (int nt = 0; nt < 8; nt++) {
            const int c0 = cw * 64 + nt * 8 + (lane & 3) * 2;
            float cq0 = csq[c0];
            float cq1 = csq[c0 + 1];
            const int i0 = kb + nt * 8 + (lane & 3) * 2;
#pragma unroll
            for (int mt = 0; mt < 2; mt++)
#pragma unroll
                for (int rh = 0; rh < 2; rh++) {
                    const int slot = mt * 2 + rh;
                    float v0 = fmaf(-2.0f, acc[(mt * 8 + nt) * 4 + rh * 2 + 0], xsq_r[slot]) + cq0;
                    float v1 = fmaf(-2.0f, acc[(mt * 8 + nt) * 4 + rh * 2 + 1], xsq_r[slot]) + cq1;
                    if (v0 < bestd[slot]) { bestd[slot] = v0; besti[slot] = i0; }
                    if (v1 < bestd[slot]) { bestd[slot] = v1; besti[slot] = i0 + 1; }
                }
        }

        __syncthreads();  // all warps done with buf before overwrite
        if (t + 2 < NTIL) {
            const float* src = g_cbB + (size_t)(t + 2) * TILE_FLOATS;
            for (int c = tid; c < 4128; c += 256) {
                unsigned dst = (c < 4096) ? (smem_b0 + buf * 65536 + c * 16)
                                          : (smem_csq + buf * 512 + (c - 4096) * 16);
                cp16(dst, src + c * 4);
            }
        }
        CP_COMMIT();
    }

    // --- merge across lane&3 (shfl), then across col-warps (smem) ---
#pragma unroll
    for (int s = 0; s < 4; s++) {
#pragma unroll
        for (int off = 1; off <= 2; off <<= 1) {
            float od = __shfl_xor_sync(0xffffffffu, bestd[s], off);
            int oi = __shfl_xor_sync(0xffffffffu, besti[s], off);
            if (od < bestd[s] || (od == bestd[s] && oi < besti[s])) {
                bestd[s] = od; besti[s] = oi;
            }
        }
    }
    float* md = (float*)(smem + OFF_MD);
    int* mi = (int*)(smem + OFF_MI);
    if ((lane & 3) == 0) {
#pragma unroll
        for (int mt = 0; mt < 2; mt++)
#pragma unroll
            for (int rh = 0; rh < 2; rh++) {
                int pt = 32 * rw + mt * 16 + rh * 8 + (lane >> 2);
                md[cw * 128 + pt] = bestd[mt * 2 + rh];
                mi[cw * 128 + pt] = besti[mt * 2 + rh];
            }
    }
    __syncthreads();

    if (tid < 128) {
        float d0 = md[tid];
        int i0 = mi[tid];
        float d1 = md[128 + tid];
        int i1 = mi[128 + tid];
        if (d1 < d0 || (d1 == d0 && i1 < i0)) { d0 = d1; i0 = i1; }

        const int pt = blockIdx.x * 128 + tid;
        o_idx[pt] = (float)i0;

        float4* q = (float4*)(o_quant + (size_t)pt * DIM);
        const float4* cr = (const float4*)(codebook + (size_t)i0 * DIM);
#pragma unroll
        for (int j = 0; j < 16; j++) q[j] = cr[j];

        atomicAdd(&g_counts[i0], 1.0f);
        const float* xr = x + (size_t)pt * DIM;
        float* es = g_embed + (size_t)i0 * DIM;
#pragma unroll
        for (int j = 0; j < DIM; j++) atomicAdd(&es[j], xr[j]);
    }
}

// ---- finalize 1: new_cluster_size, n, smoothing reciprocal ----
__global__ void finalize1_kernel(const float* __restrict__ cluster_size,
                                 float* __restrict__ o_cs) {
    __shared__ float warpsum[32];
    __shared__ float s_n;
    float local = 0.0f;
    for (int k = threadIdx.x; k < NCODES; k += blockDim.x) {
        float ncs = DECAY_F * cluster_size[k] + OMD_F * g_counts[k];
        o_cs[k] = ncs;
        g_ncs[k] = ncs;
        local += ncs;
    }
#pragma unroll
    for (int o = 16; o; o >>= 1) local += __shfl_down_sync(0xffffffffu, local, o);
    if ((threadIdx.x & 31) == 0) warpsum[threadIdx.x >> 5] = local;
    __syncthreads();
    if (threadIdx.x < 32) {
        float v = (threadIdx.x < (blockDim.x >> 5)) ? warpsum[threadIdx.x] : 0.0f;
#pragma unroll
        for (int o = 16; o; o >>= 1) v += __shfl_down_sync(0xffffffffu, v, o);
        if (threadIdx.x == 0) s_n = v;
    }
    __syncthreads();
    float n = s_n;
    float denom = n + (float)NCODES * EPS_F;
    for (int k = threadIdx.x; k < NCODES; k += blockDim.x) {
        float sm = (g_ncs[k] + EPS_F) / denom * n;
        g_factor[k] = 1.0f / sm;
    }
}

// ---- finalize 2: new_ema_w, new_codebook ----
__global__ void finalize2_kernel(const float* __restrict__ ema_w,
                                 float* __restrict__ o_cb,
                                 float* __restrict__ o_ema) {
    int i = blockIdx.x * blockDim.x + threadIdx.x;
    if (i >= NCODES * DIM) return;
    float e = DECAY_F * ema_w[i] + OMD_F * g_embed[i];
    o_ema[i] = e;
    o_cb[i] = e * g_factor[i >> 6];
}

extern "C" void kernel_launch(void* const* d_in, const int* in_sizes, int n_in,
                              void* d_out, int out_size) {
    const float* x            = (const float*)d_in[0];
    const float* codebook     = (const float*)d_in[1];
    const float* cluster_size = (const float*)d_in[2];
    const float* ema_w        = (const float*)d_in[3];

    float* out     = (float*)d_out;
    float* o_quant = out;                           // 16*4096*64
    float* o_idx   = o_quant + (size_t)NPTS * DIM;  // 16*4096
    float* o_cb    = o_idx + NPTS;                  // 4096*64
    float* o_cs    = o_cb + (size_t)NCODES * DIM;   // 4096
    float* o_ema   = o_cs + NCODES;                 // 4096*64

    static int smem_set = 0;
    if (!smem_set) {
        cudaFuncSetAttribute(vq_kernel, cudaFuncAttributeMaxDynamicSharedMemorySize, SMEM_TOTAL);
        smem_set = 1;
    }

    prep_kernel<<<(NCODES * DIM + 255) / 256, 256>>>(codebook);
    vq_kernel<<<NPTS / 128, 256, SMEM_TOTAL>>>(x, codebook, o_quant, o_idx);
    finalize1_kernel<<<1, 1024>>>(cluster_size, o_cs);
    finalize2_kernel<<<(NCODES * DIM + 255) / 256, 256>>>(ema_w, o_cb, o_ema);
}

// round 4
// speedup vs baseline: 2.2483x; 1.1940x over previous
#include <cuda_runtime.h>
#include <cuda_fp16.h>

#define NCODES 4096
#define DIM 64
#define NPTS 65536          // B*S
#define NTIL 32             // code tiles of 128
#define TILE_BYTES 16896    // 16384 fp16 B-frags + 512 csq(f32)
#define DECAY_F 0.99f
#define OMD_F 0.01f
#define EPS_F 1e-5f

// ---------------- device scratch (no allocations allowed) ----------------
__device__ float g_counts[NCODES];
__device__ float g_embed[NCODES * DIM];
__device__ float g_ncs[NCODES];
__device__ float g_factor[NCODES];
// Codebook as fp16 in m16n8k16 B-fragment order, csq(f32) appended per tile.
__device__ __align__(16) unsigned char g_cbB[NTIL * TILE_BYTES];

// ---------------- smem layout (bytes) ----------------
#define OFF_APK  0            // A frag pack: [ks4][mt8][lane32] uint4 = 16 KB
#define OFF_B    16384        // 2 x 16896 (B frags + csq)
#define OFF_CAND 50176        // 128 pts x 8 cand ints = 4 KB
#define SMEM_TOTAL 54272

static __device__ __forceinline__ void mma16(float* c, const uint4& a,
                                             unsigned b0, unsigned b1) {
    asm("mma.sync.aligned.m16n8k16.row.col.f32.f16.f16.f32 "
        "{%0,%1,%2,%3}, {%4,%5,%6,%7}, {%8,%9}, {%0,%1,%2,%3};"
        : "+f"(c[0]), "+f"(c[1]), "+f"(c[2]), "+f"(c[3])
        : "r"(a.x), "r"(a.y), "r"(a.z), "r"(a.w), "r"(b0), "r"(b1));
}
static __device__ __forceinline__ void cp16(unsigned dst, const void* src) {
    asm volatile("cp.async.cg.shared.global [%0], [%1], 16;" :: "r"(dst), "l"(src));
}
#define CP_COMMIT() asm volatile("cp.async.commit_group;" ::: "memory")
#define CP_WAIT1()  asm volatile("cp.async.wait_group 1;" ::: "memory")

// sorted ascending top-4 insert, constant-indexed
#define TOP4_INS(s, v, ix)                                                  \
    if ((v) < td##s[3]) {                                                   \
        if ((v) < td##s[2]) {                                               \
            td##s[3] = td##s[2]; ti##s[3] = ti##s[2];                       \
            if ((v) < td##s[1]) {                                           \
                td##s[2] = td##s[1]; ti##s[2] = ti##s[1];                   \
                if ((v) < td##s[0]) {                                       \
                    td##s[1] = td##s[0]; ti##s[1] = ti##s[0];               \
                    td##s[0] = (v); ti##s[0] = (ix);                        \
                } else { td##s[1] = (v); ti##s[1] = (ix); }                 \
            } else { td##s[2] = (v); ti##s[2] = (ix); }                     \
        } else { td##s[3] = (v); ti##s[3] = (ix); }                         \
    }

// ---- prep: codebook -> fp16 B-frag layout + csq; zero scratch ----
__global__ void prep_kernel(const float* __restrict__ codebook) {
    int i = blockIdx.x * blockDim.x + threadIdx.x;  // 0..262143
    if (i >= NCODES * DIM) return;
    int k = i >> 6, d = i & 63;
    float v = codebook[i];
    int tile = k >> 7, nloc = k & 127, nt = nloc >> 3, nn = nloc & 7;
    int ks = d >> 4, c = d & 15;
    int lane = nn * 4 + ((c & 7) >> 1);
    unsigned off = (unsigned)tile * TILE_BYTES +
                   (((ks * 8 + (nt >> 1)) * 32 + lane) * 16) +
                   (nt & 1) * 8 + (c >> 3) * 4 + (c & 1) * 2;
    *(__half*)(g_cbB + off) = __float2half_rn(v);
    g_embed[i] = 0.0f;
    if (d == 0) {
        g_counts[k] = 0.0f;
        const float* row = codebook + (size_t)k * DIM;
        float s = 0.0f;
#pragma unroll
        for (int j = 0; j < DIM; j++) s += row[j] * row[j];
        *(float*)(g_cbB + (unsigned)tile * TILE_BYTES + 16384 + nloc * 4) = s;
    }
}

// ---- main: fp16 1-pass mma GEMM + top-4 select + exact refine + EMA ----
__global__ void __launch_bounds__(256, 1) vq_kernel(
    const float* __restrict__ x, const float* __restrict__ codebook,
    float* __restrict__ o_quant, float* __restrict__ o_idx) {
    extern __shared__ char smem[];
    const int tid = threadIdx.x;
    const int lane = tid & 31, w = tid >> 5;
    const int rw = w >> 1, cw = w & 1;  // row-warp(32 pts), col-warp(64 codes)

    // --- prologue: pack x tile (fp16) into A-fragment layout ---
    if (tid < 128) {
        const int m = tid;
        const int mt = m >> 4, mm = m & 15, rh = mm >> 3, gr = mm & 7;
        const float4* xr = (const float4*)(x + ((size_t)blockIdx.x * 128 + m) * DIM);
#pragma unroll
        for (int j = 0; j < 16; j++) {
            float4 v4 = xr[j];
            float vv[4] = {v4.x, v4.y, v4.z, v4.w};
#pragma unroll
            for (int e = 0; e < 4; e++) {
                int d = j * 4 + e;
                int ks = d >> 4, c = d & 15;
                int ln = gr * 4 + ((c & 7) >> 1);
                int reg = (c >> 3) * 2 + rh;
                unsigned off = (((ks * 8 + mt) * 32 + ln) * 16) + reg * 4 + (c & 1) * 2;
                *(__half*)(smem + OFF_APK + off) = __float2half_rn(vv[e]);
            }
        }
    }

    // --- prefetch B tiles 0,1 ---
    const unsigned smem_b = (unsigned)__cvta_generic_to_shared(smem + OFF_B);
#pragma unroll
    for (int t = 0; t < 2; t++) {
        const unsigned char* src = g_cbB + (size_t)t * TILE_BYTES;
        for (int c = tid; c < TILE_BYTES / 16; c += 256)
            cp16(smem_b + t * TILE_BYTES + c * 16, src + c * 16);
        CP_COMMIT();
    }
    __syncthreads();

    // --- load A frags into registers ---
    uint4 afr[4][2];
    {
        const uint4* A4 = (const uint4*)(smem + OFF_APK);
#pragma unroll
        for (int ks = 0; ks < 4; ks++)
#pragma unroll
            for (int mt2 = 0; mt2 < 2; mt2++)
                afr[ks][mt2] = A4[(ks * 8 + rw * 2 + mt2) * 32 + lane];
    }

    // per-lane top-4 state, slot = mt2*2+rh
    float td0[4] = {3.4e38f, 3.4e38f, 3.4e38f, 3.4e38f}; int ti0[4] = {0, 0, 0, 0};
    float td1[4] = {3.4e38f, 3.4e38f, 3.4e38f, 3.4e38f}; int ti1[4] = {0, 0, 0, 0};
    float td2[4] = {3.4e38f, 3.4e38f, 3.4e38f, 3.4e38f}; int ti2[4] = {0, 0, 0, 0};
    float td3[4] = {3.4e38f, 3.4e38f, 3.4e38f, 3.4e38f}; int ti3[4] = {0, 0, 0, 0};

    for (int t = 0; t < NTIL; ++t) {
        const int buf = t & 1;
        CP_WAIT1();
        __syncthreads();

        float acc[64];
#pragma unroll
        for (int i = 0; i < 64; i++) acc[i] = 0.0f;

        const uint4* B4 = (const uint4*)(smem + OFF_B + buf * TILE_BYTES);
#pragma unroll
        for (int ks = 0; ks < 4; ks++)
#pragma unroll
            for (int ntp = 0; ntp < 4; ntp++) {
                uint4 b = B4[(ks * 8 + cw * 4 + ntp) * 32 + lane];
#pragma unroll
                for (int mt2 = 0; mt2 < 2; mt2++) {
                    mma16(&acc[(mt2 * 8 + ntp * 2 + 0) * 4], afr[ks][mt2], b.x, b.y);
                    mma16(&acc[(mt2 * 8 + ntp * 2 + 1) * 4], afr[ks][mt2], b.z, b.w);
                }
            }

        // --- selection epilogue: s = csq - 2*dot, top-4 per slot ---
        const float* csqS = (const float*)(smem + OFF_B + buf * TILE_BYTES + 16384);
        float csqr[16];
#pragma unroll
        for (int nt = 0; nt < 8; nt++)
#pragma unroll
            for (int h = 0; h < 2; h++)
                csqr[nt * 2 + h] = csqS[cw * 64 + nt * 8 + 2 * (lane & 3) + h];

        const int kb = t * 128 + cw * 64 + 2 * (lane & 3);
#pragma unroll
        for (int nt = 0; nt < 8; nt++)
#pragma unroll
            for (int h = 0; h < 2; h++) {
                const int ix = kb + nt * 8 + h;
                const float cq = csqr[nt * 2 + h];
                float s0 = fmaf(-2.0f, acc[(0 * 8 + nt) * 4 + 0 + h], cq);
                float s1 = fmaf(-2.0f, acc[(0 * 8 + nt) * 4 + 2 + h], cq);
                float s2 = fmaf(-2.0f, acc[(1 * 8 + nt) * 4 + 0 + h], cq);
                float s3 = fmaf(-2.0f, acc[(1 * 8 + nt) * 4 + 2 + h], cq);
                TOP4_INS(0, s0, ix);
                TOP4_INS(1, s1, ix);
                TOP4_INS(2, s2, ix);
                TOP4_INS(3, s3, ix);
            }

        __syncthreads();
        if (t + 2 < NTIL) {
            const unsigned char* src = g_cbB + (size_t)(t + 2) * TILE_BYTES;
            for (int c = tid; c < TILE_BYTES / 16; c += 256)
                cp16(smem_b + buf * TILE_BYTES + c * 16, src + c * 16);
        }
        CP_COMMIT();
    }

    // --- merge top-4 across the 4 lanes sharing each point row ---
#pragma unroll
    for (int off = 1; off <= 2; off <<= 1) {
#pragma unroll
        for (int r = 0; r < 4; r++) {
            float v; int ix;
            v = __shfl_xor_sync(0xffffffffu, td0[r], off);
            ix = __shfl_xor_sync(0xffffffffu, ti0[r], off);
            TOP4_INS(0, v, ix);
            v = __shfl_xor_sync(0xffffffffu, td1[r], off);
            ix = __shfl_xor_sync(0xffffffffu, ti1[r], off);
            TOP4_INS(1, v, ix);
            v = __shfl_xor_sync(0xffffffffu, td2[r], off);
            ix = __shfl_xor_sync(0xffffffffu, ti2[r], off);
            TOP4_INS(2, v, ix);
            v = __shfl_xor_sync(0xffffffffu, td3[r], off);
            ix = __shfl_xor_sync(0xffffffffu, ti3[r], off);
            TOP4_INS(3, v, ix);
        }
    }

    int* candS = (int*)(smem + OFF_CAND);
    if ((lane & 3) == 0) {
        const int pr = lane >> 2;
#pragma unroll
        for (int r = 0; r < 4; r++) {
            candS[(rw * 32 + 0 * 16 + 0 * 8 + pr) * 8 + cw * 4 + r] = ti0[r];
            candS[(rw * 32 + 0 * 16 + 1 * 8 + pr) * 8 + cw * 4 + r] = ti1[r];
            candS[(rw * 32 + 1 * 16 + 0 * 8 + pr) * 8 + cw * 4 + r] = ti2[r];
            candS[(rw * 32 + 1 * 16 + 1 * 8 + pr) * 8 + cw * 4 + r] = ti3[r];
        }
    }
    __syncthreads();

    // --- exact fp32 refine: warp per point, 8 candidates x 4 lanes each ---
    const int cd = lane >> 2, sub = lane & 3;
    for (int ii = 0; ii < 16; ii++) {
        const int pt = w * 16 + ii;
        const int gpt = blockIdx.x * 128 + pt;
        const int cidx = candS[pt * 8 + cd];

        const float4* xr = (const float4*)(x + (size_t)gpt * DIM) + sub * 4;
        const float4* cr = (const float4*)(codebook + (size_t)cidx * DIM) + sub * 4;
        float dot = 0.0f, xsq = 0.0f, csq = 0.0f;
#pragma unroll
        for (int j = 0; j < 4; j++) {
            float4 xa = xr[j], ca = cr[j];
            dot = fmaf(xa.x, ca.x, dot); xsq = fmaf(xa.x, xa.x, xsq); csq = fmaf(ca.x, ca.x, csq);
            dot = fmaf(xa.y, ca.y, dot); xsq = fmaf(xa.y, xa.y, xsq); csq = fmaf(ca.y, ca.y, csq);
            dot = fmaf(xa.z, ca.z, dot); xsq = fmaf(xa.z, xa.z, xsq); csq = fmaf(ca.z, ca.z, csq);
            dot = fmaf(xa.w, ca.w, dot); xsq = fmaf(xa.w, xa.w, xsq); csq = fmaf(ca.w, ca.w, csq);
        }
#pragma unroll
        for (int o = 1; o <= 2; o <<= 1) {
            dot += __shfl_xor_sync(0xffffffffu, dot, o);
            xsq += __shfl_xor_sync(0xffffffffu, xsq, o);
            csq += __shfl_xor_sync(0xffffffffu, csq, o);
        }
        float d = fmaf(-2.0f, dot, xsq) + csq;
        int wi = cidx;
#pragma unroll
        for (int o = 4; o <= 16; o <<= 1) {
            float od = __shfl_xor_sync(0xffffffffu, d, o);
            int oi = __shfl_xor_sync(0xffffffffu, wi, o);
            if (od < d || (od == d && oi < wi)) { d = od; wi = oi; }
        }

        if (lane == 0) o_idx[gpt] = (float)wi;
        ((float2*)(o_quant + (size_t)gpt * DIM))[lane] =
            ((const float2*)(codebook + (size_t)wi * DIM))[lane];
        if (lane == 0) atomicAdd(&g_counts[wi], 1.0f);
        float2 xv2 = ((const float2*)(x + (size_t)gpt * DIM))[lane];
        atomicAdd(&g_embed[(size_t)wi * DIM + 2 * lane], xv2.x);
        atomicAdd(&g_embed[(size_t)wi * DIM + 2 * lane + 1], xv2.y);
    }
}

// ---- finalize 1: new_cluster_size, n, smoothing reciprocal ----
__global__ void finalize1_kernel(const float* __restrict__ cluster_size,
                                 float* __restrict__ o_cs) {
    __shared__ float warpsum[32];
    __shared__ float s_n;
    float local = 0.0f;
    for (int k = threadIdx.x; k < NCODES; k += blockDim.x) {
        float ncs = DECAY_F * cluster_size[k] + OMD_F * g_counts[k];
        o_cs[k] = ncs;
        g_ncs[k] = ncs;
        local += ncs;
    }
#pragma unroll
    for (int o = 16; o; o >>= 1) local += __shfl_down_sync(0xffffffffu, local, o);
    if ((threadIdx.x & 31) == 0) warpsum[threadIdx.x >> 5] = local;
    __syncthreads();
    if (threadIdx.x < 32) {
        float v = (threadIdx.x < (blockDim.x >> 5)) ? warpsum[threadIdx.x] : 0.0f;
#pragma unroll
        for (int o = 16; o; o >>= 1) v += __shfl_down_sync(0xffffffffu, v, o);
        if (threadIdx.x == 0) s_n = v;
    }
    __syncthreads();
    float n = s_n;
    float denom = n + (float)NCODES * EPS_F;
    for (int k = threadIdx.x; k < NCODES; k += blockDim.x) {
        float sm = (g_ncs[k] + EPS_F) / denom * n;
        g_factor[k] = 1.0f / sm;
    }
}

// ---- finalize 2: new_ema_w, new_codebook ----
__global__ void finalize2_kernel(const float* __restrict__ ema_w,
                                 float* __restrict__ o_cb,
                                 float* __restrict__ o_ema) {
    int i = blockIdx.x * blockDim.x + threadIdx.x;
    if (i >= NCODES * DIM) return;
    float e = DECAY_F * ema_w[i] + OMD_F * g_embed[i];
    o_ema[i] = e;
    o_cb[i] = e * g_factor[i >> 6];
}

extern "C" void kernel_launch(void* const* d_in, const int* in_sizes, int n_in,
                              void* d_out, int out_size) {
    const float* x            = (const float*)d_in[0];
    const float* codebook     = (const float*)d_in[1];
    const float* cluster_size = (const float*)d_in[2];
    const float* ema_w        = (const float*)d_in[3];

    float* out     = (float*)d_out;
    float* o_quant = out;                           // 16*4096*64
    float* o_idx   = o_quant + (size_t)NPTS * DIM;  // 16*4096
    float* o_cb    = o_idx + NPTS;                  // 4096*64
    float* o_cs    = o_cb + (size_t)NCODES * DIM;   // 4096
    float* o_ema   = o_cs + NCODES;                 // 4096*64

    static int smem_set = 0;
    if (!smem_set) {
        cudaFuncSetAttribute(vq_kernel, cudaFuncAttributeMaxDynamicSharedMemorySize, SMEM_TOTAL);
        smem_set = 1;
    }

    prep_kernel<<<(NCODES * DIM + 255) / 256, 256>>>(codebook);
    vq_kernel<<<NPTS / 128, 256, SMEM_TOTAL>>>(x, codebook, o_quant, o_idx);
    finalize1_kernel<<<1, 1024>>>(cluster_size, o_cs);
    finalize2_kernel<<<(NCODES * DIM + 255) / 256, 256>>>(ema_w, o_cb, o_ema);
}